// round 15
// baseline (speedup 1.0000x reference)
#include <cuda_runtime.h>
#include <math.h>

#define NN 8192
#define DDIM 200
#define NBD 128
#define GCAP (1 << 18)
#define SCAP 3072
#define JCAP 1024
#define RCAP 256
#define GATH 512
#define NBIN 896
#define KMAX 128

__device__ float g_b[NN], g_e[NN];
__device__ float g_pb[NBD], g_pe[NBD];
__device__ int g_Ri[NN];
__device__ float g_Rb[NN];
__device__ int g_Jj[NN];
__device__ float g_Je[NN];
__device__ unsigned long long g_keys[GCAP];

__device__ __forceinline__ float dot4(float4 a, float4 w, float acc) {
    return fmaf(a.x, w.x, fmaf(a.y, w.y, fmaf(a.z, w.z, fmaf(a.w, w.w, acc))));
}
__device__ __forceinline__ unsigned f2u(float x) {
    unsigned u = __float_as_uint(x);
    return (u & 0x80000000u) ? ~u : (u | 0x80000000u);
}
__device__ __forceinline__ float u2f(unsigned u) {
    unsigned v = (u & 0x80000000u) ? (u & 0x7FFFFFFFu) : ~u;
    return __uint_as_float(v);
}
// log-linear bin of distance d (monotone non-decreasing), bins [0, NBIN) — select-2 only
__device__ __forceinline__ int logbin(unsigned d) {
    if (d < 32u) return (int)d;
    int m = 31 - __clz(d);
    return ((m - 5) << 5) + (int)((d >> (m - 5)) & 31u) + 32;
}
__device__ __forceinline__ unsigned long long binlow(int b) {
    if (b < 32) return (unsigned long long)b;
    int m = 5 + ((b - 32) >> 5);
    int sub = (b - 32) & 31;
    return (unsigned long long)(32 + sub) << (m - 5);
}

// ---------- GEMV: 128 blocks (single wave), 2 rows/warp, front-batched ----------
__global__ void __launch_bounds__(1024) k_dots(const float* __restrict__ G,
                                               const float* __restrict__ wb,
                                               const float* __restrict__ we) {
    int wid = threadIdx.x >> 5;
    int lane = threadIdx.x & 31;
    int row0 = blockIdx.x * 64 + wid * 2;
    const float4* r0 = reinterpret_cast<const float4*>(G + (size_t)row0 * DDIM);
    const float4* r1 = reinterpret_cast<const float4*>(G + (size_t)(row0 + 1) * DDIM);
    const float4* wb4 = reinterpret_cast<const float4*>(wb);
    const float4* we4 = reinterpret_cast<const float4*>(we);
    bool hasB = (lane + 32) < (DDIM / 4);
    int qb = hasB ? lane + 32 : lane;
    float4 a0 = r0[lane];
    float4 a1 = r1[lane];
    float4 a0B = r0[qb];
    float4 a1B = r1[qb];
    float4 wA = __ldg(&wb4[lane]);
    float4 eA = __ldg(&we4[lane]);
    float4 wB = __ldg(&wb4[qb]);
    float4 eB = __ldg(&we4[qb]);
    float sb0 = dot4(a0, wA, 0.f), se0 = dot4(a0, eA, 0.f);
    float sb1 = dot4(a1, wA, 0.f), se1 = dot4(a1, eA, 0.f);
    if (hasB) {
        sb0 = dot4(a0B, wB, sb0); se0 = dot4(a0B, eB, se0);
        sb1 = dot4(a1B, wB, sb1); se1 = dot4(a1B, eB, se1);
    }
#pragma unroll
    for (int o = 16; o; o >>= 1) {
        sb0 += __shfl_xor_sync(0xffffffffu, sb0, o);
        se0 += __shfl_xor_sync(0xffffffffu, se0, o);
        sb1 += __shfl_xor_sync(0xffffffffu, sb1, o);
        se1 += __shfl_xor_sync(0xffffffffu, se1, o);
    }
    __shared__ float eb[32], ee[32];
    if (lane == 0) {
        g_b[row0] = sb0;
        g_b[row0 + 1] = sb1;
        g_e[row0] = se0;
        g_e[row0 + 1] = se1;
        eb[wid] = expf(sb0) + expf(sb1);
        ee[wid] = expf(se0) + expf(se1);
    }
    __syncthreads();
    if (wid == 0) {
        float v = eb[lane];
#pragma unroll
        for (int o = 16; o; o >>= 1) v += __shfl_down_sync(0xffffffffu, v, o);
        if (lane == 0) g_pb[blockIdx.x] = v;
    } else if (wid == 1) {
        float v = ee[lane];
#pragma unroll
        for (int o = 16; o; o >>= 1) v += __shfl_down_sync(0xffffffffu, v, o);
        if (lane == 0) g_pe[blockIdx.x] = v;
    }
}

// one-warp ascending bin-find over dual-plane hist (select-2 slow path)
#define BIN_FIND_ASC(k_in)                                                       \
    do {                                                                         \
        int lsum = 0;                                                            \
        int hb = tid * (NBIN / 32);                                              \
        _Pragma("unroll") for (int t = 0; t < NBIN / 32; t++)                    \
            lsum += (int)hist[hb + t] + (int)hist[NBIN + hb + t];                \
        int pre = lsum;                                                          \
        _Pragma("unroll") for (int o = 1; o < 32; o <<= 1) {                     \
            int u = __shfl_up_sync(0xffffffffu, pre, o);                         \
            if (tid >= o) pre += u;                                              \
        }                                                                        \
        int runc = pre - lsum;                                                   \
        _Pragma("unroll") for (int t = 0; t < NBIN / 32; t++) {                  \
            int h = (int)hist[hb + t] + (int)hist[NBIN + hb + t];                \
            if (runc < (k_in) && runc + h >= (k_in)) s_kbin = hb + t;            \
            runc += h;                                                           \
        }                                                                        \
    } while (0)

__global__ void __launch_bounds__(1024) k_master(const int* __restrict__ kp,
                                                 float* __restrict__ out,
                                                 int out_size) {
    __shared__ __align__(16) unsigned long long cand[SCAP];   // 24KB
    __shared__ __align__(16) unsigned hist[2 * NBIN];         // 7KB
    __shared__ int sjidx[JCAP];
    __shared__ float sje[JCAP];                               // 8KB
    __shared__ int sri[RCAP];
    __shared__ float srb[RCAP];                               // 2KB
    __shared__ __align__(16) unsigned long long stop[GATH];   // 4KB (aliased as oh[1024])
    __shared__ float wtot[32], wexcl[32];
    __shared__ unsigned etot[32];
    __shared__ float sda[8], sdb[8];
    __shared__ float s_denom;
    __shared__ unsigned s_umax, s_vmax, s_emax;
    __shared__ int s_kbin;
    __shared__ int s_nR, s_nJ, s_cnt;
    __shared__ unsigned s_m;

    unsigned* oh = reinterpret_cast<unsigned*>(stop);   // 32 warps x 32 octaves

    int tid = threadIdx.x;
    int lane = tid & 31;
    int wid = tid >> 5;
    int plane = (wid & 1) * NBIN;
    int k = *kp;
    if (k < 1) k = 1;
    if (k > KMAX) k = KMAX;
    int base = tid * 8;

    // ---- load working set into registers (vectorized) ----
    float bi[8], el[8], cl[8];
    {
        const float4* bp = reinterpret_cast<const float4*>(g_b) + tid * 2;
        const float4* ep = reinterpret_cast<const float4*>(g_e) + tid * 2;
        float4 b0 = bp[0], b1 = bp[1], e0 = ep[0], e1 = ep[1];
        bi[0] = b0.x; bi[1] = b0.y; bi[2] = b0.z; bi[3] = b0.w;
        bi[4] = b1.x; bi[5] = b1.y; bi[6] = b1.z; bi[7] = b1.w;
        el[0] = e0.x; el[1] = e0.y; el[2] = e0.z; el[3] = e0.w;
        el[4] = e1.x; el[5] = e1.y; el[6] = e1.z; el[7] = e1.w;
    }

    // local prefix-max(b) partials; per-warp e-max to etot (race-free)
    float lex;
    {
        float run = -INFINITY;
#pragma unroll
        for (int t = 0; t < 8; t++) { run = fmaxf(run, bi[t]); cl[t] = run; }
        float incl = run;
        unsigned lem = 0u;
#pragma unroll
        for (int t = 0; t < 8; t++) lem = max(lem, f2u(el[t]));
#pragma unroll
        for (int o = 1; o < 32; o <<= 1) {
            float u = __shfl_up_sync(0xffffffffu, incl, o);
            if (lane >= o) incl = fmaxf(incl, u);
        }
#pragma unroll
        for (int o = 16; o; o >>= 1)
            lem = max(lem, __shfl_xor_sync(0xffffffffu, lem, o));
        if (lane == 31) wtot[wid] = incl;
        lex = __shfl_up_sync(0xffffffffu, incl, 1);
        if (lane == 0) {
            lex = -INFINITY;
            etot[wid] = lem;
        }
    }
    // denominator partial reduce (float)
    if (wid < 8) {
        float dv = (tid < 128) ? g_pb[tid] : g_pe[tid - 128];
#pragma unroll
        for (int o = 16; o; o >>= 1) dv += __shfl_down_sync(0xffffffffu, dv, o);
        if (lane == 0) { if (wid < 4) sda[wid] = dv; else sdb[wid - 4] = dv; }
    }
    // hist + oh clear + scalar init
    if (tid >= 512 && tid < 512 + 2 * NBIN / 4) {
        int h4 = (tid - 512) * 4;
        *reinterpret_cast<uint4*>(&hist[h4]) = make_uint4(0u, 0u, 0u, 0u);
    }
    if (tid >= 256 && tid < 512) {
        int h4 = (tid - 256) * 4;
        *reinterpret_cast<uint4*>(&oh[h4]) = make_uint4(0u, 0u, 0u, 0u);
    }
    if (tid == 0) {
        s_nR = 0; s_nJ = 0; s_m = 0; s_cnt = 0;
        s_umax = 0u; s_vmax = 0u; s_kbin = NBIN - 1;
    }
    __syncthreads();  // bar1

    if (wid == 0) {
        float incl = wtot[lane];
#pragma unroll
        for (int o = 1; o < 32; o <<= 1) {
            float u = __shfl_up_sync(0xffffffffu, incl, o);
            if (lane >= o) incl = fmaxf(incl, u);
        }
        float ex = __shfl_up_sync(0xffffffffu, incl, 1);
        if (lane == 0) ex = -INFINITY;
        wexcl[lane] = ex;
    } else if (tid == 32) {
        float a = sda[0] + sda[1] + sda[2] + sda[3];
        float b2 = sdb[0] + sdb[1] + sdb[2] + sdb[3];
        s_denom = a * b2;
    } else if (wid == 2) {
        unsigned v = etot[lane];
#pragma unroll
        for (int o = 16; o; o >>= 1)
            v = max(v, __shfl_xor_sync(0xffffffffu, v, o));
        if (lane == 0) s_emax = v;
    }
    __syncthreads();  // bar2

    // finalize c_j; per-warp c max -> shared atomic (barrier-separated from init)
    {
        float exP = fmaxf(wexcl[wid], lex);
        unsigned lmax = 0u;
#pragma unroll
        for (int t = 0; t < 8; t++) {
            cl[t] = fmaxf(cl[t], exP) + el[t];
            lmax = max(lmax, f2u(cl[t]));
        }
#pragma unroll
        for (int o = 16; o; o >>= 1)
            lmax = max(lmax, __shfl_xor_sync(0xffffffffu, lmax, o));
        if (lane == 0) atomicMax(&s_umax, lmax);
    }
    __syncthreads();  // bar3

    // ==== select-1 phase A: octave counting, warp-private rows, ZERO atomics ====
    unsigned umax = s_umax;
    float maxE = u2f(s_emax);
#pragma unroll
    for (int t = 0; t < 8; t++) {
        unsigned d = umax - f2u(cl[t]);
        int oc = 31 - __clz(d | 32u);   // 5..31, monotone coarse bin of d
        unsigned m = __match_any_sync(0xffffffffu, oc);
        if ((int)(__ffs(m) - 1) == lane)
            oh[wid * 32 + oc] += (unsigned)__popc(m);   // warp-private row: no race
    }
    __syncthreads();  // bar4

    // redundant per-warp octave reduce + select octave ko (k-th smallest d)
    int ko, kb;
    {
        int tot = 0;
#pragma unroll
        for (int w = 0; w < 32; w++) tot += (int)oh[w * 32 + lane];
        int cum = tot;
#pragma unroll
        for (int o = 1; o < 32; o <<= 1) {
            int u = __shfl_up_sync(0xffffffffu, cum, o);
            if (lane >= o) cum += u;
        }
        unsigned ball = __ballot_sync(0xffffffffu, cum >= k);
        ko = (int)(__ffs(ball) - 1);
        int before = __shfl_sync(0xffffffffu, cum - tot, ko);
        kb = k - before;   // rank within octave ko (>= 1)
    }

    // ==== select-1 phase B: fine 32 sub-bins, only octave-ko elements (~100 atomics) ====
#pragma unroll
    for (int t = 0; t < 8; t++) {
        unsigned d = umax - f2u(cl[t]);
        int oc = 31 - __clz(d | 32u);
        if (oc == ko) {
            int sub = (ko == 5) ? (int)(d >> 1) : (int)((d >> (ko - 5)) & 31u);
            atomicAdd(&hist[plane + sub], 1u);
        }
    }
    __syncthreads();  // bar5

    // redundant sub-bin find -> exact threshold edge
    unsigned ulow;
    {
        int stot_ = (int)hist[lane] + (int)hist[NBIN + lane];
        int cum = stot_;
#pragma unroll
        for (int o = 1; o < 32; o <<= 1) {
            int u = __shfl_up_sync(0xffffffffu, cum, o);
            if (lane >= o) cum += u;
        }
        unsigned ball = __ballot_sync(0xffffffffu, cum >= kb);
        int sub = (int)(__ffs(ball) - 1);
        unsigned long long dmax =
            (ko == 5) ? (unsigned long long)(2 * sub + 1)
                      : (((unsigned long long)(33 + sub) << (ko - 5)) - 1ull);
        ulow = (dmax >= (unsigned long long)umax) ? 0u : umax - (unsigned)dmax;
    }
    float T = u2f(ulow);

    // ---- build J and R lists ----
#pragma unroll
    for (int t = 0; t < 8; t++) {
        if (f2u(cl[t]) >= ulow) {
            int p = atomicAdd(&s_nJ, 1);
            if (p < JCAP) { sjidx[p] = base + t; sje[p] = el[t]; }
            else { g_Jj[p] = base + t; g_Je[p] = el[t]; }
        }
    }
#pragma unroll
    for (int t = 0; t < 8; t++) {
        if (bi[t] + maxE >= T) {   // global-max prune (superset)
            int p = atomicAdd(&s_nR, 1);
            if (p < RCAP) { sri[p] = base + t; srb[p] = bi[t]; }
            else { g_Ri[p] = base + t; g_Rb[p] = bi[t]; }
        }
    }
    __syncthreads();  // bar6

    // ---- enumerate R x J (warp per row); clear phase-B hist bins for select-2 ----
    if (tid == 0) s_kbin = NBIN - 1;
    if (wid == 31) {   // safe: all binfind reads finished before bar6
        hist[lane] = 0u;
        hist[NBIN + lane] = 0u;
    }
    {
        int nR = s_nR, nJ = s_nJ;
        unsigned lvmax = 0u;
        for (int r = wid; r < nR; r += 32) {
            int i = (r < RCAP) ? sri[r] : g_Ri[r];
            float bv = (r < RCAP) ? srb[r] : g_Rb[r];
            for (int q = lane; q < nJ; q += 32) {
                int j;
                float ej;
                if (q < JCAP) { j = sjidx[q]; ej = sje[q]; }
                else { j = g_Jj[q]; ej = g_Je[q]; }
                float s = bv + ej;
                if (j >= i && s >= T) {
                    float v = expf(s);
                    unsigned vb = __float_as_uint(v);
                    unsigned fl = (unsigned)i * NN + (unsigned)j;
                    unsigned long long key = ((unsigned long long)vb << 32) |
                                             (unsigned long long)(0xFFFFFFFFu - fl);
                    unsigned p = atomicAdd(&s_m, 1u);
                    if (p < SCAP) cand[p] = key;
                    else if (p < GCAP) g_keys[p] = key;
                    lvmax = max(lvmax, vb);
                }
            }
        }
#pragma unroll
        for (int o = 16; o; o >>= 1)
            lvmax = max(lvmax, __shfl_xor_sync(0xffffffffu, lvmax, o));
        if (lane == 0) atomicMax(&s_vmax, lvmax);
    }
    __syncthreads();  // bar7
    unsigned M = s_m;
    if (M > (unsigned)GCAP) M = (unsigned)GCAP;

    const unsigned long long* src;
    int n;
    if (M <= (unsigned)GATH) {
        src = cand;       // fast path (oh/stop alias dead; cand holds all keys)
        n = (int)M;
    } else {
        unsigned vmax = s_vmax;
        for (unsigned c = tid; c < M; c += 1024) {
            unsigned vb = (unsigned)(((c < SCAP) ? cand[c] : g_keys[c]) >> 32);
            atomicAdd(&hist[plane + logbin(vmax - vb)], 1u);
        }
        __syncthreads();  // bar8
        if (wid == 0) BIN_FIND_ASC(k);
        __syncthreads();  // bar9
        unsigned vlow;
        {
            unsigned long long dmax = binlow(s_kbin + 1) - 1ull;
            vlow = (dmax >= (unsigned long long)vmax) ? 0u : vmax - (unsigned)dmax;
        }
        for (unsigned c = tid; c < M; c += 1024) {
            unsigned long long key = (c < SCAP) ? cand[c] : g_keys[c];
            if ((unsigned)(key >> 32) >= vlow) {
                int p = atomicAdd(&s_cnt, 1);
                if (p < GATH) stop[p] = key;
            }
        }
        __syncthreads();  // bar10
        src = stop;
        n = s_cnt;
        if (n > GATH) n = GATH;
    }

    // ---- exact rank sort (value desc, flat idx asc), vectorized reads ----
    float denom = s_denom;
    if (tid < n) {
        unsigned long long mykey = src[tid];
        int rank = 0;
        const ulonglong2* s2 = reinterpret_cast<const ulonglong2*>(src);
        int half = n >> 1;
        for (int u = 0; u < half; u++) {
            ulonglong2 p = s2[u];
            rank += (p.x > mykey) + (p.y > mykey);
        }
        if (n & 1) rank += (src[n - 1] > mykey);
        if (rank < k) {
            unsigned fl = 0xFFFFFFFFu - (unsigned)(mykey & 0xFFFFFFFFull);
            unsigned ii = fl / NN, jj = fl % NN;
            float v = __uint_as_float((unsigned)(mykey >> 32));
            if (2 * rank + 1 < out_size) {
                out[2 * rank] = (float)ii;
                out[2 * rank + 1] = (float)jj;
            }
            if (2 * k + rank < out_size) out[2 * k + rank] = v / denom;
        }
    }
    for (int c = 3 * k + tid; c < out_size; c += 1024) out[c] = 0.f;
}

extern "C" void kernel_launch(void* const* d_in, const int* in_sizes, int n_in,
                              void* d_out, int out_size) {
    const float* G = (const float*)d_in[0];
    const float* wb = (const float*)d_in[1];
    const float* we = (const float*)d_in[2];
    const int* kp = (const int*)d_in[3];
    float* out = (float*)d_out;

    k_dots<<<NBD, 1024>>>(G, wb, we);
    k_master<<<1, 1024>>>(kp, out, out_size);
}

// round 16
// speedup vs baseline: 1.3589x; 1.3589x over previous
#include <cuda_runtime.h>
#include <math.h>

#define NN 8192
#define DDIM 200
#define NBD 128
#define GCAP (1 << 18)
#define SCAP 3072
#define JCAP 1024
#define RCAP 256
#define GATH 512
#define NBIN 896
#define KMAX 128

__device__ float g_b[NN], g_e[NN];
__device__ float g_pb[NBD], g_pe[NBD];
__device__ int g_Ri[NN];
__device__ float g_Rb[NN];
__device__ int g_Jj[NN];
__device__ float g_Je[NN];
__device__ unsigned long long g_keys[GCAP];

__device__ __forceinline__ float dot4(float4 a, float4 w, float acc) {
    return fmaf(a.x, w.x, fmaf(a.y, w.y, fmaf(a.z, w.z, fmaf(a.w, w.w, acc))));
}

// ---------- GEMV: 128 blocks (single wave), 2 rows/warp, front-batched loads ----------
__global__ void __launch_bounds__(1024) k_dots(const float* __restrict__ G,
                                               const float* __restrict__ wb,
                                               const float* __restrict__ we) {
    int wid = threadIdx.x >> 5;
    int lane = threadIdx.x & 31;
    int row0 = blockIdx.x * 64 + wid * 2;
    const float4* r0 = reinterpret_cast<const float4*>(G + (size_t)row0 * DDIM);
    const float4* r1 = reinterpret_cast<const float4*>(G + (size_t)(row0 + 1) * DDIM);
    const float4* wb4 = reinterpret_cast<const float4*>(wb);
    const float4* we4 = reinterpret_cast<const float4*>(we);
    bool hasB = (lane + 32) < (DDIM / 4);
    int qb = hasB ? lane + 32 : lane;
    // front-batch all independent loads for MLP
    float4 a0 = r0[lane];
    float4 a1 = r1[lane];
    float4 a0B = r0[qb];
    float4 a1B = r1[qb];
    float4 wA = __ldg(&wb4[lane]);
    float4 eA = __ldg(&we4[lane]);
    float4 wB = __ldg(&wb4[qb]);
    float4 eB = __ldg(&we4[qb]);
    float sb0 = dot4(a0, wA, 0.f), se0 = dot4(a0, eA, 0.f);
    float sb1 = dot4(a1, wA, 0.f), se1 = dot4(a1, eA, 0.f);
    if (hasB) {
        sb0 = dot4(a0B, wB, sb0); se0 = dot4(a0B, eB, se0);
        sb1 = dot4(a1B, wB, sb1); se1 = dot4(a1B, eB, se1);
    }
#pragma unroll
    for (int o = 16; o; o >>= 1) {
        sb0 += __shfl_xor_sync(0xffffffffu, sb0, o);
        se0 += __shfl_xor_sync(0xffffffffu, se0, o);
        sb1 += __shfl_xor_sync(0xffffffffu, sb1, o);
        se1 += __shfl_xor_sync(0xffffffffu, se1, o);
    }
    __shared__ float eb[32], ee[32];
    if (lane == 0) {
        g_b[row0] = sb0;
        g_b[row0 + 1] = sb1;
        g_e[row0] = se0;
        g_e[row0 + 1] = se1;
        eb[wid] = expf(sb0) + expf(sb1);
        ee[wid] = expf(se0) + expf(se1);
    }
    __syncthreads();
    if (wid == 0) {
        float v = eb[lane];
#pragma unroll
        for (int o = 16; o; o >>= 1) v += __shfl_down_sync(0xffffffffu, v, o);
        if (lane == 0) g_pb[blockIdx.x] = v;
    } else if (wid == 1) {
        float v = ee[lane];
#pragma unroll
        for (int o = 16; o; o >>= 1) v += __shfl_down_sync(0xffffffffu, v, o);
        if (lane == 0) g_pe[blockIdx.x] = v;
    }
}

__device__ __forceinline__ unsigned f2u(float x) {
    unsigned u = __float_as_uint(x);
    return (u & 0x80000000u) ? ~u : (u | 0x80000000u);
}
__device__ __forceinline__ float u2f(unsigned u) {
    unsigned v = (u & 0x80000000u) ? (u & 0x7FFFFFFFu) : ~u;
    return __uint_as_float(v);
}
// log-linear bin of distance d (monotone non-decreasing), bins [0, NBIN)
__device__ __forceinline__ int logbin(unsigned d) {
    if (d < 32u) return (int)d;
    int m = 31 - __clz(d);
    return ((m - 5) << 5) + (int)((d >> (m - 5)) & 31u) + 32;
}
// smallest d with logbin(d) == b  (64-bit to handle b == NBIN)
__device__ __forceinline__ unsigned long long binlow(int b) {
    if (b < 32) return (unsigned long long)b;
    int m = 5 + ((b - 32) >> 5);
    int sub = (b - 32) & 31;
    return (unsigned long long)(32 + sub) << (m - 5);
}

// one-warp ascending bin-find over dual-plane hist: smallest bin with cum >= k_in
#define BIN_FIND_ASC(k_in)                                                       \
    do {                                                                         \
        int lsum = 0;                                                            \
        int hb = tid * (NBIN / 32);                                              \
        _Pragma("unroll") for (int t = 0; t < NBIN / 32; t++)                    \
            lsum += (int)hist[hb + t] + (int)hist[NBIN + hb + t];                \
        int pre = lsum;                                                          \
        _Pragma("unroll") for (int o = 1; o < 32; o <<= 1) {                     \
            int u = __shfl_up_sync(0xffffffffu, pre, o);                         \
            if (tid >= o) pre += u;                                              \
        }                                                                        \
        int runc = pre - lsum;                                                   \
        _Pragma("unroll") for (int t = 0; t < NBIN / 32; t++) {                  \
            int h = (int)hist[hb + t] + (int)hist[NBIN + hb + t];                \
            if (runc < (k_in) && runc + h >= (k_in)) s_kbin = hb + t;            \
            runc += h;                                                           \
        }                                                                        \
    } while (0)

__global__ void __launch_bounds__(1024) k_master(const int* __restrict__ kp,
                                                 float* __restrict__ out,
                                                 int out_size) {
    __shared__ __align__(16) unsigned long long cand[SCAP];   // 24KB
    __shared__ __align__(16) unsigned hist[2 * NBIN];         // 7KB (dual plane)
    __shared__ int sjidx[JCAP];
    __shared__ float sje[JCAP];                               // 8KB
    __shared__ int sri[RCAP];
    __shared__ float srb[RCAP];                               // 2KB
    __shared__ unsigned long long stop[GATH];                 // 4KB
    __shared__ float wtot[32], wexcl[32];
    __shared__ float sda[8], sdb[8];
    __shared__ float s_denom;
    __shared__ unsigned s_umax, s_vmax, s_emax;
    __shared__ int s_kbin;
    __shared__ int s_nR, s_nJ, s_cnt;
    __shared__ unsigned s_m;

    int tid = threadIdx.x;
    int lane = tid & 31;
    int wid = tid >> 5;
    int plane = (wid & 1) * NBIN;
    int k = *kp;
    if (k < 1) k = 1;
    if (k > KMAX) k = KMAX;
    int base = tid * 8;

    // ---- load working set into registers (vectorized) ----
    float bi[8], el[8], cl[8];
    {
        const float4* bp = reinterpret_cast<const float4*>(g_b) + tid * 2;
        const float4* ep = reinterpret_cast<const float4*>(g_e) + tid * 2;
        float4 b0 = bp[0], b1 = bp[1], e0 = ep[0], e1 = ep[1];
        bi[0] = b0.x; bi[1] = b0.y; bi[2] = b0.z; bi[3] = b0.w;
        bi[4] = b1.x; bi[5] = b1.y; bi[6] = b1.z; bi[7] = b1.w;
        el[0] = e0.x; el[1] = e0.y; el[2] = e0.z; el[3] = e0.w;
        el[4] = e1.x; el[5] = e1.y; el[6] = e1.z; el[7] = e1.w;
    }

    // local prefix-max(b) partials + e-max
    float lex;
    {
        float run = -INFINITY;
#pragma unroll
        for (int t = 0; t < 8; t++) { run = fmaxf(run, bi[t]); cl[t] = run; }
        float incl = run;
#pragma unroll
        for (int o = 1; o < 32; o <<= 1) {
            float u = __shfl_up_sync(0xffffffffu, incl, o);
            if (lane >= o) incl = fmaxf(incl, u);
        }
        if (lane == 31) wtot[wid] = incl;
        lex = __shfl_up_sync(0xffffffffu, incl, 1);
        if (lane == 0) lex = -INFINITY;
    }
    // denominator partial reduce (float)
    if (wid < 8) {
        float dv = (tid < 128) ? g_pb[tid] : g_pe[tid - 128];
#pragma unroll
        for (int o = 16; o; o >>= 1) dv += __shfl_down_sync(0xffffffffu, dv, o);
        if (lane == 0) { if (wid < 4) sda[wid] = dv; else sdb[wid - 4] = dv; }
    }
    // hist clear + scalar init
    if (tid >= 512 && tid < 512 + 2 * NBIN / 4) {
        int h4 = (tid - 512) * 4;
        *reinterpret_cast<uint4*>(&hist[h4]) = make_uint4(0u, 0u, 0u, 0u);
    }
    if (tid == 0) {
        s_nR = 0; s_nJ = 0; s_m = 0; s_cnt = 0;
        s_umax = 0u; s_vmax = 0u; s_emax = 0u; s_kbin = NBIN - 1;
    }
    // e-max (global, for R pruning)
    {
        unsigned lem = 0u;
#pragma unroll
        for (int t = 0; t < 8; t++) lem = max(lem, f2u(el[t]));
#pragma unroll
        for (int o = 16; o; o >>= 1)
            lem = max(lem, __shfl_xor_sync(0xffffffffu, lem, o));
        if (lane == 0) atomicMax(&s_emax, lem);
    }
    __syncthreads();  // bar1

    if (wid == 0) {
        float incl = wtot[lane];
#pragma unroll
        for (int o = 1; o < 32; o <<= 1) {
            float u = __shfl_up_sync(0xffffffffu, incl, o);
            if (lane >= o) incl = fmaxf(incl, u);
        }
        float ex = __shfl_up_sync(0xffffffffu, incl, 1);
        if (lane == 0) ex = -INFINITY;
        wexcl[lane] = ex;
    } else if (tid == 32) {
        float a = sda[0] + sda[1] + sda[2] + sda[3];
        float b2 = sdb[0] + sdb[1] + sdb[2] + sdb[3];
        s_denom = a * b2;
    }
    __syncthreads();  // bar2

    // finalize c_j; per-warp c max -> shared atomic
    {
        float exP = fmaxf(wexcl[wid], lex);
        unsigned lmax = 0u;
#pragma unroll
        for (int t = 0; t < 8; t++) {
            cl[t] = fmaxf(cl[t], exP) + el[t];
            lmax = max(lmax, f2u(cl[t]));
        }
#pragma unroll
        for (int o = 16; o; o >>= 1)
            lmax = max(lmax, __shfl_xor_sync(0xffffffffu, lmax, o));
        if (lane == 0) atomicMax(&s_umax, lmax);
    }
    __syncthreads();  // bar3

    // ---- select-1: one-pass log-linear histogram on d = umax - f2u(c) ----
    unsigned umax = s_umax;
    float maxE = u2f(s_emax);
#pragma unroll
    for (int t = 0; t < 8; t++)
        atomicAdd(&hist[plane + logbin(umax - f2u(cl[t]))], 1u);
    __syncthreads();  // bar4
    if (wid == 0) BIN_FIND_ASC(k);
    __syncthreads();  // bar5
    unsigned ulow;
    {
        unsigned long long dmax = binlow(s_kbin + 1) - 1ull;
        ulow = (dmax >= (unsigned long long)umax) ? 0u : umax - (unsigned)dmax;
    }
    float T = u2f(ulow);

    // ---- build J and R lists; clear hist ----
#pragma unroll
    for (int t = 0; t < 8; t++) {
        if (f2u(cl[t]) >= ulow) {
            int p = atomicAdd(&s_nJ, 1);
            if (p < JCAP) { sjidx[p] = base + t; sje[p] = el[t]; }
            else { g_Jj[p] = base + t; g_Je[p] = el[t]; }
        }
    }
#pragma unroll
    for (int t = 0; t < 8; t++) {
        if (bi[t] + maxE >= T) {   // global-max prune (superset)
            int p = atomicAdd(&s_nR, 1);
            if (p < RCAP) { sri[p] = base + t; srb[p] = bi[t]; }
            else { g_Ri[p] = base + t; g_Rb[p] = bi[t]; }
        }
    }
    if (tid >= 512 && tid < 512 + 2 * NBIN / 4) {
        int h4 = (tid - 512) * 4;
        *reinterpret_cast<uint4*>(&hist[h4]) = make_uint4(0u, 0u, 0u, 0u);
    }
    __syncthreads();  // bar6

    // ---- enumerate R x J (warp per row); track value-bit max ----
    if (tid == 0) s_kbin = NBIN - 1;
    {
        int nR = s_nR, nJ = s_nJ;
        unsigned lvmax = 0u;
        for (int r = wid; r < nR; r += 32) {
            int i = (r < RCAP) ? sri[r] : g_Ri[r];
            float bv = (r < RCAP) ? srb[r] : g_Rb[r];
            for (int q = lane; q < nJ; q += 32) {
                int j;
                float ej;
                if (q < JCAP) { j = sjidx[q]; ej = sje[q]; }
                else { j = g_Jj[q]; ej = g_Je[q]; }
                float s = bv + ej;
                if (j >= i && s >= T) {
                    float v = expf(s);
                    unsigned vb = __float_as_uint(v);
                    unsigned fl = (unsigned)i * NN + (unsigned)j;
                    unsigned long long key = ((unsigned long long)vb << 32) |
                                             (unsigned long long)(0xFFFFFFFFu - fl);
                    unsigned p = atomicAdd(&s_m, 1u);
                    if (p < SCAP) cand[p] = key;
                    else if (p < GCAP) g_keys[p] = key;
                    lvmax = max(lvmax, vb);
                }
            }
        }
#pragma unroll
        for (int o = 16; o; o >>= 1)
            lvmax = max(lvmax, __shfl_xor_sync(0xffffffffu, lvmax, o));
        if (lane == 0) atomicMax(&s_vmax, lvmax);
    }
    __syncthreads();  // bar7
    unsigned M = s_m;
    if (M > (unsigned)GCAP) M = (unsigned)GCAP;
    unsigned vmax = s_vmax;

    // ---- select-2: one-pass log-linear histogram over value bits ----
    for (unsigned c = tid; c < M; c += 1024) {
        unsigned vb = (unsigned)(((c < SCAP) ? cand[c] : g_keys[c]) >> 32);
        atomicAdd(&hist[plane + logbin(vmax - vb)], 1u);
    }
    __syncthreads();  // bar8
    if (wid == 0) BIN_FIND_ASC(k);   // if M < k, preset NBIN-1 stands (gather all)
    __syncthreads();  // bar9
    unsigned vlow;
    {
        unsigned long long dmax = binlow(s_kbin + 1) - 1ull;
        vlow = (dmax >= (unsigned long long)vmax) ? 0u : vmax - (unsigned)dmax;
    }

    // ---- gather all candidates with value-bits >= vlow (superset of top-k) ----
    for (unsigned c = tid; c < M; c += 1024) {
        unsigned long long key = (c < SCAP) ? cand[c] : g_keys[c];
        if ((unsigned)(key >> 32) >= vlow) {
            int p = atomicAdd(&s_cnt, 1);
            if (p < GATH) stop[p] = key;
        }
    }
    __syncthreads();  // bar10
    int n = s_cnt;
    if (n > GATH) n = GATH;

    // ---- exact rank sort over gathered keys (value desc, flat idx asc) ----
    float denom = s_denom;
    if (tid < n) {
        unsigned long long mykey = stop[tid];
        int rank = 0;
        for (int u = 0; u < n; u++) rank += (stop[u] > mykey);
        if (rank < k) {
            unsigned fl = 0xFFFFFFFFu - (unsigned)(mykey & 0xFFFFFFFFull);
            unsigned ii = fl / NN, jj = fl % NN;
            float v = __uint_as_float((unsigned)(mykey >> 32));
            if (2 * rank + 1 < out_size) {
                out[2 * rank] = (float)ii;
                out[2 * rank + 1] = (float)jj;
            }
            if (2 * k + rank < out_size) out[2 * k + rank] = v / denom;
        }
    }
    for (int c = 3 * k + tid; c < out_size; c += 1024) out[c] = 0.f;
}

extern "C" void kernel_launch(void* const* d_in, const int* in_sizes, int n_in,
                              void* d_out, int out_size) {
    const float* G = (const float*)d_in[0];
    const float* wb = (const float*)d_in[1];
    const float* we = (const float*)d_in[2];
    const int* kp = (const int*)d_in[3];
    float* out = (float*)d_out;

    k_dots<<<NBD, 1024>>>(G, wb, we);
    k_master<<<1, 1024>>>(kp, out, out_size);
}